// round 5
// baseline (speedup 1.0000x reference)
#include <cuda_runtime.h>

#define NBLK 148
#define NTHR 512
#define NWARP (NBLK*16)
#define NL 6
#define DD 512
#define FF 2048
#define TD 1536

// ---------------- device scratch ----------------
__device__ __align__(16) float g_src35[35*DD];
__device__ __align__(16) float g_kv[NL*5*7*1024];
__device__ __align__(16) float g_q0[NL*5*DD];
__device__ __align__(16) float g_ctx5[NL*5*DD];
__device__ __align__(16) float g_vm[NL*5*DD];
__device__ __align__(16) float g_aggv[NL*DD];
__device__ __align__(16) float g_x0[7*DD];
__device__ __align__(16) float g_qkv0[7*TD];
__device__ __align__(16) float g_msgN[6*DD];
__device__ __align__(16) float g_aggn[DD];
__device__ __align__(16) float g_h[7*DD];
__device__ __align__(16) float g_hid[7*FF];
__device__ __align__(16) float g_y[7*DD];
__device__ unsigned g_bar;

// ---------------- helpers ----------------
__device__ __forceinline__ float wred(float v) {
#pragma unroll
    for (int o = 16; o; o >>= 1) v += __shfl_xor_sync(0xffffffffu, v, o);
    return v;
}
__device__ __forceinline__ float d4(float4 a, float4 b) {
    return fmaf(a.x, b.x, fmaf(a.y, b.y, fmaf(a.z, b.z, a.w * b.w)));
}
__device__ __forceinline__ void gridbar() {
    __syncthreads();
    if (threadIdx.x == 0) {
        unsigned old;
        asm volatile("atom.release.gpu.add.u32 %0, [%1], %2;"
                     : "=r"(old) : "l"(&g_bar), "r"(1u) : "memory");
        unsigned target = (old / NBLK + 1u) * NBLK;
        unsigned cur;
        do {
            asm volatile("ld.acquire.gpu.u32 %0, [%1];" : "=r"(cur) : "l"(&g_bar) : "memory");
        } while (cur < target);
    }
    __syncthreads();
}
__device__ __forceinline__ void pf_range(const float* base, int nfloats, int gt) {
    const char* p = (const char*)base;
    int nlines = nfloats >> 5;
    for (int i = gt; i < nlines; i += NBLK*NTHR)
        asm volatile("prefetch.global.L2 [%0];" :: "l"(p + (size_t)i*128));
}
__device__ __forceinline__ void ldw(const float* w, float4* wv) {
    const float4* wr = (const float4*)w;
    int lane = threadIdx.x & 31;
#pragma unroll
    for (int i = 0; i < 4; i++) wv[i] = __ldg(&wr[lane + 32*i]);
}
template<int K, int STR>
__device__ __forceinline__ void dotK(const float4* wv, const float* smbase, float* res) {
    int lane = threadIdx.x & 31;
    float acc[K];
#pragma unroll
    for (int k = 0; k < K; k++) {
        const float4* s4 = (const float4*)(smbase + k*STR);
        float a0 = d4(wv[0], s4[lane]);
        float a1 = d4(wv[1], s4[lane+32]);
        float a2 = d4(wv[2], s4[lane+64]);
        float a3 = d4(wv[3], s4[lane+96]);
        acc[k] = (a0 + a1) + (a2 + a3);
    }
#pragma unroll
    for (int o = 16; o; o >>= 1)
#pragma unroll
        for (int k = 0; k < K; k++)
            acc[k] += __shfl_xor_sync(0xffffffffu, acc[k], o);
#pragma unroll
    for (int k = 0; k < K; k++) res[k] = acc[k];
}
template<int NIT>
__device__ __forceinline__ float dot_long(const float* w, const float* smbase) {
    int lane = threadIdx.x & 31;
    const float4* wr = (const float4*)w;
    const float4* s4 = (const float4*)smbase;
    float a[4] = {0.f, 0.f, 0.f, 0.f};
#pragma unroll
    for (int i = 0; i < NIT; i += 4) {
        a[0] += d4(__ldg(&wr[lane + 32*(i+0)]), s4[lane + 32*(i+0)]);
        a[1] += d4(__ldg(&wr[lane + 32*(i+1)]), s4[lane + 32*(i+1)]);
        a[2] += d4(__ldg(&wr[lane + 32*(i+2)]), s4[lane + 32*(i+2)]);
        a[3] += d4(__ldg(&wr[lane + 32*(i+3)]), s4[lane + 32*(i+3)]);
    }
    return wred((a[0] + a[1]) + (a[2] + a[3]));
}
__device__ __forceinline__ void ln_row(const float* __restrict__ x,
                                       const float* __restrict__ add,
                                       const float* __restrict__ w,
                                       const float* __restrict__ b,
                                       float* __restrict__ out) {
    int lane = threadIdx.x & 31;
    float v[16]; float s = 0.f;
#pragma unroll
    for (int j = 0; j < 16; j++) {
        float t = x[j*32 + lane];
        if (add) t += add[j*32 + lane];
        v[j] = t; s += t;
    }
    s = wred(s);
    float mu = s * (1.f/512.f);
    float q = 0.f;
#pragma unroll
    for (int j = 0; j < 16; j++) { float d = v[j] - mu; q += d*d; }
    q = wred(q);
    float rs = rsqrtf(q * (1.f/512.f) + 1e-5f);
#pragma unroll
    for (int j = 0; j < 16; j++)
        out[j*32 + lane] = (v[j] - mu) * rs * w[j*32 + lane] + b[j*32 + lane];
}

__global__ void __launch_bounds__(NTHR)
fused_kernel(const float* __restrict__ feat, const float* __restrict__ role,
             const float* __restrict__ in_w, const float* __restrict__ in_b,
             const float* __restrict__ out_w, const float* __restrict__ out_b,
             const float* __restrict__ ln1w, const float* __restrict__ ln1b,
             const float* __restrict__ ln2w, const float* __restrict__ ln2b,
             const float* __restrict__ ln3w, const float* __restrict__ ln3b,
             const float* __restrict__ ln4w, const float* __restrict__ ln4b,
             const float* __restrict__ f1w1, const float* __restrict__ f1b1,
             const float* __restrict__ f1w2, const float* __restrict__ f1b2,
             const float* __restrict__ f2w1, const float* __restrict__ f2b1,
             const float* __restrict__ f2w2, const float* __restrict__ f2b2,
             const float* __restrict__ a1w, const float* __restrict__ a1b,
             const float* __restrict__ a2w, const float* __restrict__ a2b,
             float* __restrict__ out)
{
    extern __shared__ float sm[];
    const int tid = threadIdx.x, lane = tid & 31, warp = tid >> 5;
    const int gw = blockIdx.x * (NTHR/32) + warp;
    const int gt = blockIdx.x * NTHR + tid;

    // ---- Phase A: src for batches 1..5 ----
    for (int i = gt; i < 35*DD; i += NBLK*NTHR) {
        int b5 = i / (7*DD); int rem = i % (7*DD); int s = rem / DD; int d = rem % DD;
        float v = feat[((b5+1)*7 + s)*DD + d];
        if (s > 0) v += role[((b5+1)*6 + (s-1))*DD + d];
        g_src35[i] = v;
    }
    pf_range(in_w, NL*TD*DD, gt);
    gridbar();

    // ---- Phase P1: K,V for (l,b>=1,s) and Q(token0), software-pipelined ----
    for (int i = tid; i < 35*DD; i += NTHR) sm[i] = g_src35[i];
    __syncthreads();
    {
        const int NT1 = NL*1024 + NL*DD;  // 9216
        int t = gw;
        if (t < NT1) {
            float4 wv[4];
            {
                const float* rp = (t < NL*1024)
                    ? in_w + ((size_t)(t >> 10)*TD + 512 + (t & 1023))*DD
                    : in_w + ((size_t)((t - NL*1024) >> 9)*TD + ((t - NL*1024) & 511))*DD;
                ldw(rp, wv);
            }
            for (;;) {
                int tn = t + NWARP;
                float4 wn[4];
                if (tn < NT1) {
                    const float* rp = (tn < NL*1024)
                        ? in_w + ((size_t)(tn >> 10)*TD + 512 + (tn & 1023))*DD
                        : in_w + ((size_t)((tn - NL*1024) >> 9)*TD + ((tn - NL*1024) & 511))*DD;
                    ldw(rp, wn);
                }
                if (t < NL*1024) {
                    int l = t >> 10, e = t & 1023;
                    float bias = in_b[l*TD + 512 + e];
                    float res[7];
#pragma unroll
                    for (int g = 0; g < 5; g++) {
                        dotK<7, DD>(wv, sm + g*7*DD, res);
                        if (lane == 0) {
#pragma unroll
                            for (int j = 0; j < 7; j++)
                                g_kv[((size_t)(l*5 + g)*7 + j)*1024 + e] = res[j] + bias;
                        }
                    }
                } else {
                    int t2 = t - NL*1024;
                    int l = t2 >> 9, e = t2 & 511;
                    float bias = in_b[l*TD + e];
                    float res[5];
                    dotK<5, 7*DD>(wv, sm, res);
                    if (lane == 0) {
#pragma unroll
                        for (int j = 0; j < 5; j++)
                            g_q0[(l*5 + j)*DD + e] = res[j] + bias;
                    }
                }
                if (tn >= NT1) break;
#pragma unroll
                for (int i = 0; i < 4; i++) wv[i] = wn[i];
                t = tn;
            }
        }
    }
    pf_range(out_w, NL*DD*DD, gt);
    pf_range(a1w, NL*DD*2560, gt);
    gridbar();

    // ---- Phase P2a: attention token0 for (l, b>=1): 30 CTA tasks ----
    if (blockIdx.x < 30) {
        int l = blockIdx.x / 5, b5 = blockIdx.x % 5;
        float* sq = sm; float* sk = sm + DD; float* satt = sm + DD + 7*DD;
        const float* kvb = g_kv + (size_t)(l*5 + b5)*7*1024;
        for (int i = tid; i < DD; i += NTHR) sq[i] = g_q0[(l*5 + b5)*DD + i];
        for (int i = tid; i < 7*DD; i += NTHR) { int s = i >> 9, d = i & 511; sk[i] = kvb[s*1024 + d]; }
        __syncthreads();
        if (tid < 56) {
            int h = tid / 7, s = tid % 7;
            float a = 0.f;
            for (int d = 0; d < 64; d++) a += sq[h*64 + d] * sk[s*DD + h*64 + d];
            satt[tid] = a * 0.125f;
        }
        __syncthreads();
        if (tid < 8) {
            float m = -1e30f;
            for (int s = 0; s < 7; s++) m = fmaxf(m, satt[tid*7 + s]);
            float e[7], su = 0.f;
            for (int s = 0; s < 7; s++) { e[s] = expf(satt[tid*7 + s] - m); su += e[s]; }
            for (int s = 0; s < 7; s++) satt[tid*7 + s] = e[s] / su;
        }
        __syncthreads();
        for (int ch = tid; ch < DD; ch += NTHR) {
            int h = ch >> 6;
            float a = 0.f;
            for (int s = 0; s < 7; s++) a += satt[h*7 + s] * kvb[s*1024 + 512 + ch];
            g_ctx5[(l*5 + b5)*DD + ch] = a;
        }
    }
    gridbar();

    // ---- Phase P2b: verb msgs ----
    for (int i = tid; i < 30*DD; i += NTHR) sm[i] = g_ctx5[i];
    __syncthreads();
    for (int t = gw; t < NL*DD; t += NWARP) {
        int l = t / DD, e = t % DD;
        float4 wv[4]; ldw(out_w + ((size_t)l*DD + e)*DD, wv);
        float bias = out_b[l*DD + e];
        float res[5];
        dotK<5, DD>(wv, sm + l*5*DD, res);
        if (lane == 0) {
#pragma unroll
            for (int j = 0; j < 5; j++)
                g_vm[(l*5 + j)*DD + e] = res[j] + bias;
        }
    }
    gridbar();

    // ---- Phase P3: agg_verb ----
    for (int i = tid; i < 30*DD; i += NTHR) sm[i] = g_vm[i];
    __syncthreads();
    for (int t = gw; t < NL*DD; t += NWARP) {
        int l = t / DD, e = t % DD;
        float a = dot_long<20>(a1w + ((size_t)l*DD + e)*2560, sm + l*5*DD);
        if (lane == 0) g_aggv[l*DD + e] = 1.f / (1.f + expf(-(a + a1b[l*DD + e])));
    }
    gridbar();

    // ================= serial layer loop =================
    for (int l = 0; l < NL; l++) {
        // ---- F1: x0 = LN24(y_prev) redundant; src = x0 + role; qkv all 7 tokens ----
        {
            float* sx0 = sm;           // 3584
            float* ssrc = sm + 3584;   // 3584
            if (l == 0) {
                for (int i = tid; i < 7*DD; i += NTHR) sx0[i] = feat[i];
            } else if (warp < 7) {
                const float* w = (warp == 0) ? (ln4w + (l-1)*DD) : (ln2w + (l-1)*DD);
                const float* b = (warp == 0) ? (ln4b + (l-1)*DD) : (ln2b + (l-1)*DD);
                ln_row(g_y + warp*DD, nullptr, w, b, sx0 + warp*DD);
            }
            __syncthreads();
            for (int i = tid; i < 7*DD; i += NTHR) {
                int s = i >> 9, d = i & 511;
                float v = sx0[i];
                if (s > 0) v += role[(s-1)*DD + d];
                ssrc[i] = v;
            }
            if (blockIdx.x == 0)
                for (int i = tid; i < 7*DD; i += NTHR) g_x0[i] = sx0[i];
            __syncthreads();
            for (int t = gw; t < TD; t += NWARP) {
                float4 wv[4]; ldw(in_w + ((size_t)l*TD + t)*DD, wv);
                float bias = in_b[l*TD + t];
                float res[7];
                dotK<7, DD>(wv, ssrc, res);
                if (lane == 0) {
#pragma unroll
                    for (int s = 0; s < 7; s++)
                        g_qkv0[s*TD + t] = res[s] + bias;
                }
            }
            pf_range(out_w + (size_t)l*DD*DD, DD*DD, gt);
            pf_range(f1w1 + (size_t)l*FF*DD, FF*DD, gt);
        }
        gridbar();

        // ---- F2: attention + LN1 (redundant) ; msg GEMV + FFN1-up (grid) ----
        {
            float* sh1  = sm;            // 3584 (rows 1..6 used)
            float* sqkv = sm + 3584;     // 10752
            float* sctx = sm + 14336;    // 3072
            float* satt = sm + 17408;    // 336
            if (warp >= 1 && warp < 7)
                ln_row(g_x0 + warp*DD, g_aggv + l*DD, ln1w + l*DD, ln1b + l*DD, sh1 + warp*DD);
            for (int i = tid; i < 7*TD; i += NTHR) sqkv[i] = g_qkv0[i];
            __syncthreads();
            for (int t = tid; t < 336; t += NTHR) {
                int qi = t / 56, r = t % 56, h = r / 7, s = r % 7;
                const float* qv = sqkv + (qi+1)*TD + h*64;
                const float* kv = sqkv + s*TD + 512 + h*64;
                float a0 = 0.f, a1 = 0.f, a2 = 0.f, a3 = 0.f;
#pragma unroll
                for (int d = 0; d < 64; d += 4) {
                    a0 = fmaf(qv[d],   kv[d],   a0);
                    a1 = fmaf(qv[d+1], kv[d+1], a1);
                    a2 = fmaf(qv[d+2], kv[d+2], a2);
                    a3 = fmaf(qv[d+3], kv[d+3], a3);
                }
                satt[t] = ((a0 + a1) + (a2 + a3)) * 0.125f;
            }
            __syncthreads();
            if (tid < 48) {
                float m = -1e30f;
                for (int s = 0; s < 7; s++) m = fmaxf(m, satt[tid*7 + s]);
                float e[7], su = 0.f;
                for (int s = 0; s < 7; s++) { e[s] = expf(satt[tid*7 + s] - m); su += e[s]; }
                for (int s = 0; s < 7; s++) satt[tid*7 + s] = e[s] / su;
            }
            __syncthreads();
            for (int i = tid; i < 6*DD; i += NTHR) {
                int qi = i >> 9, ch = i & 511, h = ch >> 6;
                float a = 0.f;
                for (int s = 0; s < 7; s++) a += satt[qi*56 + h*7 + s] * sqkv[s*TD + 1024 + ch];
                sctx[i] = a;
            }
            __syncthreads();
            if (blockIdx.x == 0)
                for (int i = 512 + tid; i < 7*DD; i += NTHR) g_h[i] = sh1[i];
            for (int t = gw; t < 512 + FF; t += NWARP) {
                if (t < 512) {
                    float4 wv[4]; ldw(out_w + ((size_t)l*DD + t)*DD, wv);
                    float res[6];
                    dotK<6, DD>(wv, sctx, res);
                    if (lane == 0) {
                        float bias = out_b[l*DD + t];
#pragma unroll
                        for (int r = 0; r < 6; r++)
                            g_msgN[r*DD + t] = res[r] + bias;
                    }
                } else {
                    int e = t - 512;
                    float4 wv[4]; ldw(f1w1 + ((size_t)l*FF + e)*DD, wv);
                    float res[6];
                    dotK<6, DD>(wv, sh1 + DD, res);
                    if (lane == 0) {
                        float bias = f1b1[l*FF + e];
#pragma unroll
                        for (int r = 0; r < 6; r++)
                            g_hid[(r+1)*FF + e] = fmaxf(res[r] + bias, 0.f);
                    }
                }
            }
            pf_range(a2w + (size_t)l*DD*3072, DD*3072, gt);
            pf_range(f1w2 + (size_t)l*DD*FF, DD*FF, gt);
        }
        gridbar();

        // ---- F3: agg_noun GEMV + FFN1-down rows 1-6 (grid) ----
        {
            float* smsg = sm;          // 3072
            float* shid = sm + 3072;   // 12288
            for (int i = tid; i < 6*DD; i += NTHR) smsg[i] = g_msgN[i];
            for (int i = tid; i < 6*FF; i += NTHR) shid[i] = g_hid[FF + i];
            __syncthreads();
            for (int t = gw; t < 1024; t += NWARP) {
                if (t < 512) {
                    float a = dot_long<24>(a2w + ((size_t)l*DD + t)*3072, smsg);
                    if (lane == 0) g_aggn[t] = 1.f / (1.f + expf(-(a + a2b[l*DD + t])));
                } else {
                    int e = t - 512;
                    const float4* wr = (const float4*)(f1w2 + ((size_t)l*DD + e)*FF);
                    float acc[6] = {0,0,0,0,0,0};
#pragma unroll
                    for (int i = 0; i < 16; i++) {
                        float4 w4 = __ldg(&wr[lane + 32*i]);
#pragma unroll
                        for (int r = 0; r < 6; r++)
                            acc[r] += d4(w4, ((const float4*)(shid + r*FF))[lane + 32*i]);
                    }
#pragma unroll
                    for (int o = 16; o; o >>= 1)
#pragma unroll
                        for (int r = 0; r < 6; r++)
                            acc[r] += __shfl_xor_sync(0xffffffffu, acc[r], o);
                    if (lane == 0) {
                        float bias = f1b2[l*DD + e];
#pragma unroll
                        for (int r = 0; r < 6; r++)
                            g_y[(r+1)*DD + e] = acc[r] + bias + g_h[(r+1)*DD + e];
                    }
                }
            }
            pf_range(f2w1 + (size_t)l*FF*DD, FF*DD, gt);
        }
        gridbar();

        // ---- F4: LN3 (redundant) + FFN2-up row 0 ----
        {
            float* sh0 = sm;
            if (warp == 0)
                ln_row(g_x0, g_aggn, ln3w + l*DD, ln3b + l*DD, sh0);
            __syncthreads();
            if (blockIdx.x == 0)
                for (int i = tid; i < DD; i += NTHR) g_h[i] = sh0[i];
            for (int t = gw; t < FF; t += NWARP) {
                float4 wv[4]; ldw(f2w1 + ((size_t)l*FF + t)*DD, wv);
                float res[1];
                dotK<1, DD>(wv, sh0, res);
                if (lane == 0) g_hid[t] = fmaxf(res[0] + f2b1[l*FF + t], 0.f);
            }
            pf_range(f2w2 + (size_t)l*DD*FF, DD*FF, gt);
        }
        gridbar();

        // ---- F5: FFN2-down row 0 ----
        {
            float* sh = sm;   // 2048
            for (int i = tid; i < FF; i += NTHR) sh[i] = g_hid[i];
            __syncthreads();
            for (int t = gw; t < DD; t += NWARP) {
                float a = dot_long<16>(f2w2 + ((size_t)l*DD + t)*FF, sh);
                if (lane == 0) g_y[t] = a + f2b2[l*DD + t] + g_h[t];
            }
            if (l + 1 < NL)
                pf_range(in_w + (size_t)(l+1)*TD*DD, TD*DD, gt);
        }
        gridbar();
    }

    // ---- output: final LN24 of g_y -> out ----
    if (blockIdx.x == 0 && warp < 7) {
        const float* w = (warp == 0) ? (ln4w + 5*DD) : (ln2w + 5*DD);
        const float* b = (warp == 0) ? (ln4b + 5*DD) : (ln2b + 5*DD);
        ln_row(g_y + warp*DD, nullptr, w, b, out + warp*DD);
    }
}

#define SMEM_BYTES 73728

extern "C" void kernel_launch(void* const* d_in, const int* in_sizes, int n_in,
                              void* d_out, int out_size) {
    cudaFuncSetAttribute(fused_kernel, cudaFuncAttributeMaxDynamicSharedMemorySize, SMEM_BYTES);
    fused_kernel<<<NBLK, NTHR, SMEM_BYTES>>>(
        (const float*)d_in[0],  (const float*)d_in[1],
        (const float*)d_in[2],  (const float*)d_in[3],
        (const float*)d_in[4],  (const float*)d_in[5],
        (const float*)d_in[6],  (const float*)d_in[7],
        (const float*)d_in[8],  (const float*)d_in[9],
        (const float*)d_in[10], (const float*)d_in[11],
        (const float*)d_in[12], (const float*)d_in[13],
        (const float*)d_in[14], (const float*)d_in[15],
        (const float*)d_in[16], (const float*)d_in[17],
        (const float*)d_in[18], (const float*)d_in[19],
        (const float*)d_in[20], (const float*)d_in[21],
        (const float*)d_in[22], (const float*)d_in[23],
        (const float*)d_in[24], (const float*)d_in[25],
        (float*)d_out);
}

// round 6
// speedup vs baseline: 1.0880x; 1.0880x over previous
#include <cuda_runtime.h>

#define NBLK 148
#define NTHR 512
#define NWARP (NBLK*16)
#define NL 6
#define DD 512
#define FF 2048
#define TD 1536
#define NBAR 35ULL

// ---------------- device scratch ----------------
__device__ __align__(16) float g_src35[35*DD];
__device__ __align__(16) float g_kv[NL*5*7*1024];
__device__ __align__(16) float g_q0[NL*5*DD];
__device__ __align__(16) float g_ctx5[NL*5*DD];
__device__ __align__(16) float g_vm[NL*5*DD];
__device__ __align__(16) float g_aggv[NL*DD];
__device__ __align__(16) float g_x0[7*DD];
__device__ __align__(16) float g_qkv0[7*TD];
__device__ __align__(16) float g_msgN[6*DD];
__device__ __align__(16) float g_aggn[DD];
__device__ __align__(16) float g_h[7*DD];
__device__ __align__(16) float g_hid[7*FF];
__device__ __align__(16) float g_y[7*DD];
__device__ unsigned long long g_bar;

// ---------------- helpers ----------------
__device__ __forceinline__ float wred(float v) {
#pragma unroll
    for (int o = 16; o; o >>= 1) v += __shfl_xor_sync(0xffffffffu, v, o);
    return v;
}
__device__ __forceinline__ float d4(float4 a, float4 b) {
    return fmaf(a.x, b.x, fmaf(a.y, b.y, fmaf(a.z, b.z, a.w * b.w)));
}
// Low-contention grid barrier: RED arrival (no return) + backoff poll.
// base = per-launch starting value of g_bar (multiple of NBAR*NBLK); idx = 1..NBAR.
__device__ __forceinline__ void gridbar(unsigned long long base, int idx) {
    __syncthreads();
    if (threadIdx.x == 0) {
        asm volatile("red.release.gpu.add.u64 [%0], %1;"
                     :: "l"(&g_bar), "l"(1ULL) : "memory");
        unsigned long long target = base + (unsigned long long)idx * NBLK;
        unsigned long long cur;
        for (;;) {
            asm volatile("ld.acquire.gpu.u64 %0, [%1];"
                         : "=l"(cur) : "l"(&g_bar) : "memory");
            if (cur >= target) break;
            __nanosleep(100);
        }
    }
    __syncthreads();
}
__device__ __forceinline__ void pf_range(const float* base, int nfloats, int gt) {
    const char* p = (const char*)base;
    int nlines = nfloats >> 5;
    for (int i = gt; i < nlines; i += NBLK*NTHR)
        asm volatile("prefetch.global.L2 [%0];" :: "l"(p + (size_t)i*128));
}
// float4 copy global->smem, block-cooperative (n multiple of 4)
__device__ __forceinline__ void cp4(float* dst, const float* src, int n) {
    float4* d4p = (float4*)dst;
    const float4* s4p = (const float4*)src;
    for (int i = threadIdx.x; i < (n >> 2); i += NTHR) d4p[i] = s4p[i];
}
__device__ __forceinline__ void ldw(const float* w, float4* wv) {
    const float4* wr = (const float4*)w;
    int lane = threadIdx.x & 31;
#pragma unroll
    for (int i = 0; i < 4; i++) wv[i] = __ldg(&wr[lane + 32*i]);
}
template<int K, int STR>
__device__ __forceinline__ void dotK(const float4* wv, const float* smbase, float* res) {
    int lane = threadIdx.x & 31;
    float acc[K];
#pragma unroll
    for (int k = 0; k < K; k++) {
        const float4* s4 = (const float4*)(smbase + k*STR);
        float a0 = d4(wv[0], s4[lane]);
        float a1 = d4(wv[1], s4[lane+32]);
        float a2 = d4(wv[2], s4[lane+64]);
        float a3 = d4(wv[3], s4[lane+96]);
        acc[k] = (a0 + a1) + (a2 + a3);
    }
#pragma unroll
    for (int o = 16; o; o >>= 1)
#pragma unroll
        for (int k = 0; k < K; k++)
            acc[k] += __shfl_xor_sync(0xffffffffu, acc[k], o);
#pragma unroll
    for (int k = 0; k < K; k++) res[k] = acc[k];
}
template<int NIT>
__device__ __forceinline__ float dot_long(const float* w, const float* smbase) {
    int lane = threadIdx.x & 31;
    const float4* wr = (const float4*)w;
    const float4* s4 = (const float4*)smbase;
    float a[4] = {0.f, 0.f, 0.f, 0.f};
#pragma unroll
    for (int i = 0; i < NIT; i += 4) {
        a[0] += d4(__ldg(&wr[lane + 32*(i+0)]), s4[lane + 32*(i+0)]);
        a[1] += d4(__ldg(&wr[lane + 32*(i+1)]), s4[lane + 32*(i+1)]);
        a[2] += d4(__ldg(&wr[lane + 32*(i+2)]), s4[lane + 32*(i+2)]);
        a[3] += d4(__ldg(&wr[lane + 32*(i+3)]), s4[lane + 32*(i+3)]);
    }
    return wred((a[0] + a[1]) + (a[2] + a[3]));
}
__device__ __forceinline__ void ln_row(const float* __restrict__ x,
                                       const float* __restrict__ add,
                                       const float* __restrict__ w,
                                       const float* __restrict__ b,
                                       float* __restrict__ out) {
    int lane = threadIdx.x & 31;
    float v[16]; float s = 0.f;
#pragma unroll
    for (int j = 0; j < 16; j++) {
        float t = x[j*32 + lane];
        if (add) t += add[j*32 + lane];
        v[j] = t; s += t;
    }
    s = wred(s);
    float mu = s * (1.f/512.f);
    float q = 0.f;
#pragma unroll
    for (int j = 0; j < 16; j++) { float d = v[j] - mu; q += d*d; }
    q = wred(q);
    float rs = rsqrtf(q * (1.f/512.f) + 1e-5f);
#pragma unroll
    for (int j = 0; j < 16; j++)
        out[j*32 + lane] = (v[j] - mu) * rs * w[j*32 + lane] + b[j*32 + lane];
}

__global__ void __launch_bounds__(NTHR)
fused_kernel(const float* __restrict__ feat, const float* __restrict__ role,
             const float* __restrict__ in_w, const float* __restrict__ in_b,
             const float* __restrict__ out_w, const float* __restrict__ out_b,
             const float* __restrict__ ln1w, const float* __restrict__ ln1b,
             const float* __restrict__ ln2w, const float* __restrict__ ln2b,
             const float* __restrict__ ln3w, const float* __restrict__ ln3b,
             const float* __restrict__ ln4w, const float* __restrict__ ln4b,
             const float* __restrict__ f1w1, const float* __restrict__ f1b1,
             const float* __restrict__ f1w2, const float* __restrict__ f1b2,
             const float* __restrict__ f2w1, const float* __restrict__ f2b1,
             const float* __restrict__ f2w2, const float* __restrict__ f2b2,
             const float* __restrict__ a1w, const float* __restrict__ a1b,
             const float* __restrict__ a2w, const float* __restrict__ a2b,
             float* __restrict__ out)
{
    extern __shared__ float sm[];
    const int tid = threadIdx.x, lane = tid & 31, warp = tid >> 5;
    const int gw = blockIdx.x * (NTHR/32) + warp;
    const int gt = blockIdx.x * NTHR + tid;

    // per-launch barrier base (replay-safe: g_bar is a multiple of NBAR*NBLK
    // between launches, and barrier 1 cannot release before every CTA reads it)
    unsigned long long bbase = 0;
    if (tid == 0) {
        unsigned long long cur;
        asm volatile("ld.relaxed.gpu.u64 %0, [%1];" : "=l"(cur) : "l"(&g_bar));
        bbase = cur - (cur % (NBAR * (unsigned long long)NBLK));
    }
    int bi = 0;

    // ---- Phase A: src for batches 1..5 ----
    for (int i = gt; i < 35*DD; i += NBLK*NTHR) {
        int b5 = i / (7*DD); int rem = i % (7*DD); int s = rem / DD; int d = rem % DD;
        float v = feat[((b5+1)*7 + s)*DD + d];
        if (s > 0) v += role[((b5+1)*6 + (s-1))*DD + d];
        g_src35[i] = v;
    }
    pf_range(in_w, NL*TD*DD, gt);
    gridbar(bbase, ++bi);

    // ---- Phase P1: K,V for (l,b>=1,s) and Q(token0) ----
    cp4(sm, g_src35, 35*DD);
    __syncthreads();
    for (int t = gw; t < NL*1024 + NL*DD; t += NWARP) {
        if (t < NL*1024) {
            int l = t >> 10, e = t & 1023;
            float4 wv[4]; ldw(in_w + ((size_t)l*TD + 512 + e)*DD, wv);
            float bias = in_b[l*TD + 512 + e];
            float res[7];
#pragma unroll
            for (int g = 0; g < 5; g++) {
                dotK<7, DD>(wv, sm + g*7*DD, res);
                if (lane == 0) {
#pragma unroll
                    for (int j = 0; j < 7; j++)
                        g_kv[((size_t)(l*5 + g)*7 + j)*1024 + e] = res[j] + bias;
                }
            }
        } else {
            int t2 = t - NL*1024;
            int l = t2 >> 9, e = t2 & 511;
            float4 wv[4]; ldw(in_w + ((size_t)l*TD + e)*DD, wv);
            float bias = in_b[l*TD + e];
            float res[5];
            dotK<5, 7*DD>(wv, sm, res);
            if (lane == 0) {
#pragma unroll
                for (int j = 0; j < 5; j++)
                    g_q0[(l*5 + j)*DD + e] = res[j] + bias;
            }
        }
    }
    pf_range(out_w, NL*DD*DD, gt);
    pf_range(a1w, NL*DD*2560, gt);
    gridbar(bbase, ++bi);

    // ---- Phase P2a: attention token0 for (l, b>=1): 30 CTA tasks ----
    if (blockIdx.x < 30) {
        int l = blockIdx.x / 5, b5 = blockIdx.x % 5;
        float* sq = sm; float* sk = sm + DD; float* satt = sm + DD + 7*DD;
        const float* kvb = g_kv + (size_t)(l*5 + b5)*7*1024;
        cp4(sq, g_q0 + (l*5 + b5)*DD, DD);
        cp4(sk, kvb, 7*DD);  // NOTE: kv rows are 1024-stride; copy below fixes layout
        __syncthreads();
        // overwrite with correct strided copy (k at offset 0 of each 1024 row)
        for (int i = tid; i < 7*DD; i += NTHR) { int s = i >> 9, d = i & 511; sk[i] = kvb[s*1024 + d]; }
        __syncthreads();
        if (tid < 56) {
            int h = tid / 7, s = tid % 7;
            float a = 0.f;
            for (int d = 0; d < 64; d++) a += sq[h*64 + d] * sk[s*DD + h*64 + d];
            satt[tid] = a * 0.125f;
        }
        __syncthreads();
        if (tid < 8) {
            float m = -1e30f;
            for (int s = 0; s < 7; s++) m = fmaxf(m, satt[tid*7 + s]);
            float e[7], su = 0.f;
            for (int s = 0; s < 7; s++) { e[s] = expf(satt[tid*7 + s] - m); su += e[s]; }
            for (int s = 0; s < 7; s++) satt[tid*7 + s] = e[s] / su;
        }
        __syncthreads();
        for (int ch = tid; ch < DD; ch += NTHR) {
            int h = ch >> 6;
            float a = 0.f;
            for (int s = 0; s < 7; s++) a += satt[h*7 + s] * kvb[s*1024 + 512 + ch];
            g_ctx5[(l*5 + b5)*DD + ch] = a;
        }
    }
    gridbar(bbase, ++bi);

    // ---- Phase P2b: verb msgs ----
    cp4(sm, g_ctx5, 30*DD);
    __syncthreads();
    for (int t = gw; t < NL*DD; t += NWARP) {
        int l = t / DD, e = t % DD;
        float4 wv[4]; ldw(out_w + ((size_t)l*DD + e)*DD, wv);
        float bias = out_b[l*DD + e];
        float res[5];
        dotK<5, DD>(wv, sm + l*5*DD, res);
        if (lane == 0) {
#pragma unroll
            for (int j = 0; j < 5; j++)
                g_vm[(l*5 + j)*DD + e] = res[j] + bias;
        }
    }
    gridbar(bbase, ++bi);

    // ---- Phase P3: agg_verb ----
    cp4(sm, g_vm, 30*DD);
    __syncthreads();
    for (int t = gw; t < NL*DD; t += NWARP) {
        int l = t / DD, e = t % DD;
        float a = dot_long<20>(a1w + ((size_t)l*DD + e)*2560, sm + l*5*DD);
        if (lane == 0) g_aggv[l*DD + e] = 1.f / (1.f + expf(-(a + a1b[l*DD + e])));
    }
    gridbar(bbase, ++bi);

    // ================= serial layer loop =================
    for (int l = 0; l < NL; l++) {
        // ---- F1: x0 = LN24(y_prev) redundant; src = x0 + role; qkv ----
        {
            float* sx0 = sm;           // 3584
            float* ssrc = sm + 3584;   // 3584
            if (l == 0) {
                cp4(sx0, feat, 7*DD);
            } else if (warp < 7) {
                const float* w = (warp == 0) ? (ln4w + (l-1)*DD) : (ln2w + (l-1)*DD);
                const float* b = (warp == 0) ? (ln4b + (l-1)*DD) : (ln2b + (l-1)*DD);
                ln_row(g_y + warp*DD, nullptr, w, b, sx0 + warp*DD);
            }
            __syncthreads();
            for (int i = tid; i < 7*DD; i += NTHR) {
                int s = i >> 9, d = i & 511;
                float v = sx0[i];
                if (s > 0) v += role[(s-1)*DD + d];
                ssrc[i] = v;
            }
            if (blockIdx.x == 0)
                for (int i = tid; i < 7*DD; i += NTHR) g_x0[i] = sx0[i];
            __syncthreads();
            for (int t = gw; t < TD; t += NWARP) {
                float4 wv[4]; ldw(in_w + ((size_t)l*TD + t)*DD, wv);
                float bias = in_b[l*TD + t];
                float res[7];
                dotK<7, DD>(wv, ssrc, res);
                if (lane == 0) {
#pragma unroll
                    for (int s = 0; s < 7; s++)
                        g_qkv0[s*TD + t] = res[s] + bias;
                }
            }
            pf_range(out_w + (size_t)l*DD*DD, DD*DD, gt);
            pf_range(f1w1 + (size_t)l*FF*DD, FF*DD, gt);
        }
        gridbar(bbase, ++bi);

        // ---- F2: attention + LN1 (redundant); msg GEMV + FFN1-up (grid) ----
        {
            float* sh1  = sm;            // 3584 (rows 1..6 used)
            float* sqkv = sm + 3584;     // 10752
            float* sctx = sm + 14336;    // 3072
            float* satt = sm + 17408;    // 336
            if (warp >= 1 && warp < 7)
                ln_row(g_x0 + warp*DD, g_aggv + l*DD, ln1w + l*DD, ln1b + l*DD, sh1 + warp*DD);
            cp4(sqkv, g_qkv0, 7*TD);
            __syncthreads();
            for (int t = tid; t < 336; t += NTHR) {
                int qi = t / 56, r = t % 56, h = r / 7, s = r % 7;
                const float* qv = sqkv + (qi+1)*TD + h*64;
                const float* kv = sqkv + s*TD + 512 + h*64;
                float a0 = 0.f, a1 = 0.f, a2 = 0.f, a3 = 0.f;
#pragma unroll
                for (int d = 0; d < 64; d += 4) {
                    a0 = fmaf(qv[d],   kv[d],   a0);
                    a1 = fmaf(qv[d+1], kv[d+1], a1);
                    a2 = fmaf(qv[d+2], kv[d+2], a2);
                    a3 = fmaf(qv[d+3], kv[d+3], a3);
                }
                satt[t] = ((a0 + a1) + (a2 + a3)) * 0.125f;
            }
            __syncthreads();
            if (tid < 48) {
                float m = -1e30f;
                for (int s = 0; s < 7; s++) m = fmaxf(m, satt[tid*7 + s]);
                float e[7], su = 0.f;
                for (int s = 0; s < 7; s++) { e[s] = expf(satt[tid*7 + s] - m); su += e[s]; }
                for (int s = 0; s < 7; s++) satt[tid*7 + s] = e[s] / su;
            }
            __syncthreads();
            for (int i = tid; i < 6*DD; i += NTHR) {
                int qi = i >> 9, ch = i & 511, h = ch >> 6;
                float a = 0.f;
                for (int s = 0; s < 7; s++) a += satt[qi*56 + h*7 + s] * sqkv[s*TD + 1024 + ch];
                sctx[i] = a;
            }
            __syncthreads();
            if (blockIdx.x == 0)
                for (int i = 512 + tid; i < 7*DD; i += NTHR) g_h[i] = sh1[i];
            for (int t = gw; t < 512 + FF; t += NWARP) {
                if (t < 512) {
                    float4 wv[4]; ldw(out_w + ((size_t)l*DD + t)*DD, wv);
                    float res[6];
                    dotK<6, DD>(wv, sctx, res);
                    if (lane == 0) {
                        float bias = out_b[l*DD + t];
#pragma unroll
                        for (int r = 0; r < 6; r++)
                            g_msgN[r*DD + t] = res[r] + bias;
                    }
                } else {
                    int e = t - 512;
                    float4 wv[4]; ldw(f1w1 + ((size_t)l*FF + e)*DD, wv);
                    float res[6];
                    dotK<6, DD>(wv, sh1 + DD, res);
                    if (lane == 0) {
                        float bias = f1b1[l*FF + e];
#pragma unroll
                        for (int r = 0; r < 6; r++)
                            g_hid[(r+1)*FF + e] = fmaxf(res[r] + bias, 0.f);
                    }
                }
            }
            pf_range(a2w + (size_t)l*DD*3072, DD*3072, gt);
            pf_range(f1w2 + (size_t)l*DD*FF, DD*FF, gt);
        }
        gridbar(bbase, ++bi);

        // ---- F3: agg_noun GEMV + FFN1-down rows 1-6 (grid) ----
        {
            float* smsg = sm;          // 3072
            float* shid = sm + 3072;   // 12288
            cp4(smsg, g_msgN, 6*DD);
            cp4(shid, g_hid + FF, 6*FF);
            __syncthreads();
            for (int t = gw; t < 1024; t += NWARP) {
                if (t < 512) {
                    float a = dot_long<24>(a2w + ((size_t)l*DD + t)*3072, smsg);
                    if (lane == 0) g_aggn[t] = 1.f / (1.f + expf(-(a + a2b[l*DD + t])));
                } else {
                    int e = t - 512;
                    const float4* wr = (const float4*)(f1w2 + ((size_t)l*DD + e)*FF);
                    float acc[6] = {0,0,0,0,0,0};
#pragma unroll
                    for (int i = 0; i < 16; i++) {
                        float4 w4 = __ldg(&wr[lane + 32*i]);
#pragma unroll
                        for (int r = 0; r < 6; r++)
                            acc[r] += d4(w4, ((const float4*)(shid + r*FF))[lane + 32*i]);
                    }
#pragma unroll
                    for (int o = 16; o; o >>= 1)
#pragma unroll
                        for (int r = 0; r < 6; r++)
                            acc[r] += __shfl_xor_sync(0xffffffffu, acc[r], o);
                    if (lane == 0) {
                        float bias = f1b2[l*DD + e];
#pragma unroll
                        for (int r = 0; r < 6; r++)
                            g_y[(r+1)*DD + e] = acc[r] + bias + g_h[(r+1)*DD + e];
                    }
                }
            }
            pf_range(f2w1 + (size_t)l*FF*DD, FF*DD, gt);
        }
        gridbar(bbase, ++bi);

        // ---- F4: LN3 (redundant) + FFN2-up row 0 ----
        {
            float* sh0 = sm;
            if (warp == 0)
                ln_row(g_x0, g_aggn, ln3w + l*DD, ln3b + l*DD, sh0);
            __syncthreads();
            if (blockIdx.x == 0)
                for (int i = tid; i < DD; i += NTHR) g_h[i] = sh0[i];
            for (int t = gw; t < FF; t += NWARP) {
                float4 wv[4]; ldw(f2w1 + ((size_t)l*FF + t)*DD, wv);
                float res[1];
                dotK<1, DD>(wv, sh0, res);
                if (lane == 0) g_hid[t] = fmaxf(res[0] + f2b1[l*FF + t], 0.f);
            }
            pf_range(f2w2 + (size_t)l*DD*FF, DD*FF, gt);
        }
        gridbar(bbase, ++bi);

        // ---- F5: FFN2-down row 0 ----
        {
            float* sh = sm;   // 2048
            cp4(sh, g_hid, FF);
            __syncthreads();
            for (int t = gw; t < DD; t += NWARP) {
                float a = dot_long<16>(f2w2 + ((size_t)l*DD + t)*FF, sh);
                if (lane == 0) g_y[t] = a + f2b2[l*DD + t] + g_h[t];
            }
            if (l + 1 < NL)
                pf_range(in_w + (size_t)(l+1)*TD*DD, TD*DD, gt);
        }
        gridbar(bbase, ++bi);
    }

    // ---- output: final LN24 of g_y -> out ----
    if (blockIdx.x == 0 && warp < 7) {
        const float* w = (warp == 0) ? (ln4w + 5*DD) : (ln2w + 5*DD);
        const float* b = (warp == 0) ? (ln4b + 5*DD) : (ln2b + 5*DD);
        ln_row(g_y + warp*DD, nullptr, w, b, out + warp*DD);
    }
}

#define SMEM_BYTES 73728

extern "C" void kernel_launch(void* const* d_in, const int* in_sizes, int n_in,
                              void* d_out, int out_size) {
    cudaFuncSetAttribute(fused_kernel, cudaFuncAttributeMaxDynamicSharedMemorySize, SMEM_BYTES);
    fused_kernel<<<NBLK, NTHR, SMEM_BYTES>>>(
        (const float*)d_in[0],  (const float*)d_in[1],
        (const float*)d_in[2],  (const float*)d_in[3],
        (const float*)d_in[4],  (const float*)d_in[5],
        (const float*)d_in[6],  (const float*)d_in[7],
        (const float*)d_in[8],  (const float*)d_in[9],
        (const float*)d_in[10], (const float*)d_in[11],
        (const float*)d_in[12], (const float*)d_in[13],
        (const float*)d_in[14], (const float*)d_in[15],
        (const float*)d_in[16], (const float*)d_in[17],
        (const float*)d_in[18], (const float*)d_in[19],
        (const float*)d_in[20], (const float*)d_in[21],
        (const float*)d_in[22], (const float*)d_in[23],
        (const float*)d_in[24], (const float*)d_in[25],
        (float*)d_out);
}

// round 9
// speedup vs baseline: 1.1505x; 1.0575x over previous
#include <cuda_runtime.h>

#define NBLK 148
#define NTHR 512
#define NWPC 16
#define NWARP (NBLK*NWPC)
#define NL 6
#define DD 512
#define FF 2048
#define TD 1536
#define NBAR 35ULL

// ---------------- device scratch ----------------
__device__ __align__(16) float g_src35[35*DD];
__device__ __align__(16) float g_kv[NL*5*7*1024];
__device__ __align__(16) float g_q0[NL*5*DD];
__device__ __align__(16) float g_ctx5[NL*5*DD];
__device__ __align__(16) float g_vm[NL*5*DD];
__device__ __align__(16) float g_aggv[NL*DD];
__device__ __align__(16) float g_qkv0[7*TD];
__device__ __align__(16) float g_msgN[6*DD];
__device__ __align__(16) float g_aggnraw[DD];
__device__ __align__(16) float g_hid[7*FF];   // [0..FF): t-path hid, [FF..7FF): rows1-6
__device__ __align__(16) float g_yraw[7*DD];  // row0: t-path RAW matvec; rows1-6: s-path (bias+resid included)
__device__ unsigned long long g_bar;

// ---------------- helpers ----------------
__device__ __forceinline__ float wred(float v) {
#pragma unroll
    for (int o = 16; o; o >>= 1) v += __shfl_xor_sync(0xffffffffu, v, o);
    return v;
}
__device__ __forceinline__ float d4(float4 a, float4 b) {
    return fmaf(a.x, b.x, fmaf(a.y, b.y, fmaf(a.z, b.z, a.w * b.w)));
}
__device__ __forceinline__ void gridbar(unsigned long long base, int idx) {
    __syncthreads();
    if (threadIdx.x == 0) {
        asm volatile("red.release.gpu.add.u64 [%0], %1;" :: "l"(&g_bar), "l"(1ULL) : "memory");
        unsigned long long target = base + (unsigned long long)idx * NBLK;
        unsigned long long cur;
        for (;;) {
            asm volatile("ld.acquire.gpu.u64 %0, [%1];" : "=l"(cur) : "l"(&g_bar) : "memory");
            if (cur >= target) break;
            __nanosleep(64);
        }
    }
    __syncthreads();
}
__device__ __forceinline__ void pf_range(const float* base, int nfloats, int gt) {
    const char* p = (const char*)base;
    int nlines = nfloats >> 5;
    for (int i = gt; i < nlines; i += NBLK*NTHR)
        asm volatile("prefetch.global.L2 [%0];" :: "l"(p + (size_t)i*128));
}
__device__ __forceinline__ void cp4(float* dst, const float* src, int n) {
    float4* d4p = (float4*)dst;
    const float4* s4p = (const float4*)src;
    for (int i = threadIdx.x; i < (n >> 2); i += NTHR) d4p[i] = s4p[i];
}
__device__ __forceinline__ void ldw(const float* w, float4* wv) {
    const float4* wr = (const float4*)w;
    int lane = threadIdx.x & 31;
#pragma unroll
    for (int i = 0; i < 4; i++) wv[i] = __ldg(&wr[lane + 32*i]);
}
template<int K, int STR>
__device__ __forceinline__ void dotK(const float4* wv, const float* smbase, float* res) {
    int lane = threadIdx.x & 31;
    float acc[K];
#pragma unroll
    for (int k = 0; k < K; k++) {
        const float4* s4 = (const float4*)(smbase + k*STR);
        float a0 = d4(wv[0], s4[lane]);
        float a1 = d4(wv[1], s4[lane+32]);
        float a2 = d4(wv[2], s4[lane+64]);
        float a3 = d4(wv[3], s4[lane+96]);
        acc[k] = (a0 + a1) + (a2 + a3);
    }
#pragma unroll
    for (int o = 16; o; o >>= 1)
#pragma unroll
        for (int k = 0; k < K; k++)
            acc[k] += __shfl_xor_sync(0xffffffffu, acc[k], o);
#pragma unroll
    for (int k = 0; k < K; k++) res[k] = acc[k];
}
template<int NIT>
__device__ __forceinline__ float dot_long(const float* w, const float* smbase) {
    int lane = threadIdx.x & 31;
    const float4* wr = (const float4*)w;
    const float4* s4 = (const float4*)smbase;
    float a[4] = {0.f, 0.f, 0.f, 0.f};
#pragma unroll
    for (int i = 0; i < NIT; i += 4) {
        a[0] += d4(__ldg(&wr[lane + 32*(i+0)]), s4[lane + 32*(i+0)]);
        a[1] += d4(__ldg(&wr[lane + 32*(i+1)]), s4[lane + 32*(i+1)]);
        a[2] += d4(__ldg(&wr[lane + 32*(i+2)]), s4[lane + 32*(i+2)]);
        a[3] += d4(__ldg(&wr[lane + 32*(i+3)]), s4[lane + 32*(i+3)]);
    }
    return wred((a[0] + a[1]) + (a[2] + a[3]));
}
template<typename G>
__device__ __forceinline__ void ln_rowf(G get, const float* __restrict__ w,
                                        const float* __restrict__ b,
                                        float* __restrict__ out) {
    int lane = threadIdx.x & 31;
    float v[16]; float s = 0.f;
#pragma unroll
    for (int j = 0; j < 16; j++) { v[j] = get(j*32 + lane); s += v[j]; }
    s = wred(s);
    float mu = s * (1.f/512.f);
    float q = 0.f;
#pragma unroll
    for (int j = 0; j < 16; j++) { float d = v[j] - mu; q += d*d; }
    q = wred(q);
    float rs = rsqrtf(q * (1.f/512.f) + 1e-5f);
#pragma unroll
    for (int j = 0; j < 16; j++)
        out[j*32 + lane] = (v[j] - mu) * rs * w[j*32 + lane] + b[j*32 + lane];
}

__global__ void __launch_bounds__(NTHR)
fused_kernel(const float* __restrict__ feat, const float* __restrict__ role,
             const float* __restrict__ in_w, const float* __restrict__ in_b,
             const float* __restrict__ out_w, const float* __restrict__ out_b,
             const float* __restrict__ ln1w, const float* __restrict__ ln1b,
             const float* __restrict__ ln2w, const float* __restrict__ ln2b,
             const float* __restrict__ ln3w, const float* __restrict__ ln3b,
             const float* __restrict__ ln4w, const float* __restrict__ ln4b,
             const float* __restrict__ f1w1, const float* __restrict__ f1b1,
             const float* __restrict__ f1w2, const float* __restrict__ f1b2,
             const float* __restrict__ f2w1, const float* __restrict__ f2b1,
             const float* __restrict__ f2w2, const float* __restrict__ f2b2,
             const float* __restrict__ a1w, const float* __restrict__ a1b,
             const float* __restrict__ a2w, const float* __restrict__ a2b,
             float* __restrict__ out)
{
    extern __shared__ float sm[];
    float* psx  = sm;          // 7*512  persistent x rows
    float* psh1 = sm + 3584;   // 6*512  persistent LN1 output (s residual)
    float* psh0 = sm + 6656;   // 512    persistent LN3 output (t residual)
    float* sc   = sm + 7168;   // scratch
    const int tid = threadIdx.x, lane = tid & 31, warp = tid >> 5;
    const int gw = blockIdx.x * NWPC + warp;
    const int gt = blockIdx.x * NTHR + tid;

    unsigned long long bbase = 0;
    if (tid == 0) {
        unsigned long long cur;
        asm volatile("ld.relaxed.gpu.u64 %0, [%1];" : "=l"(cur) : "l"(&g_bar));
        bbase = cur - (cur % (NBAR * (unsigned long long)NBLK));
    }
    int bi = 0;
    float4 pw[4];

    // ---- Phase A: src for batches 1..5 ----
    pf_range(in_w, NL*TD*DD, gt);
    for (int i = gt; i < 35*DD; i += NBLK*NTHR) {
        int b5 = i / (7*DD); int rem = i % (7*DD); int s = rem / DD; int d = rem % DD;
        float v = feat[((b5+1)*7 + s)*DD + d];
        if (s > 0) v += role[((b5+1)*6 + (s-1))*DD + d];
        g_src35[i] = v;
    }
    // preload P1 first task
    {
        int t = gw;
        const float* rp = (t < NL*1024)
            ? in_w + ((size_t)(t >> 10)*TD + 512 + (t & 1023))*DD
            : in_w + ((size_t)((t - NL*1024) >> 9)*TD + ((t - NL*1024) & 511))*DD;
        ldw(rp, pw);
    }
    gridbar(bbase, ++bi);

    // ---- P1: K,V for (l,b>=1,s) and Q(token0) ----
    cp4(sc, g_src35, 35*DD);
    __syncthreads();
    for (int t = gw; t < NL*1024 + NL*DD; t += NWARP) {
        float4 wv[4];
        if (t == gw) { wv[0]=pw[0]; wv[1]=pw[1]; wv[2]=pw[2]; wv[3]=pw[3]; }
        else {
            const float* rp = (t < NL*1024)
                ? in_w + ((size_t)(t >> 10)*TD + 512 + (t & 1023))*DD
                : in_w + ((size_t)((t - NL*1024) >> 9)*TD + ((t - NL*1024) & 511))*DD;
            ldw(rp, wv);
        }
        if (t < NL*1024) {
            int l = t >> 10, e = t & 1023;
            float bias = in_b[l*TD + 512 + e];
            float res[7];
#pragma unroll
            for (int g = 0; g < 5; g++) {
                dotK<7, DD>(wv, sc + g*7*DD, res);
                if (lane == 0)
#pragma unroll
                    for (int j = 0; j < 7; j++)
                        g_kv[((size_t)(l*5 + g)*7 + j)*1024 + e] = res[j] + bias;
            }
        } else {
            int t2 = t - NL*1024;
            int l = t2 >> 9, e = t2 & 511;
            float bias = in_b[l*TD + e];
            float res[5];
            dotK<5, 7*DD>(wv, sc, res);
            if (lane == 0)
#pragma unroll
                for (int j = 0; j < 5; j++)
                    g_q0[(l*5 + j)*DD + e] = res[j] + bias;
        }
    }
    pf_range(out_w, NL*DD*DD, gt);
    pf_range(a1w, NL*DD*2560, gt);
    // preload P2b task (held across P2a)
    if (gw < NL*DD) ldw(out_w + ((size_t)(gw >> 9)*DD + (gw & 511))*DD, pw);
    gridbar(bbase, ++bi);

    // ---- P2a: attention token0 for (l, b>=1): 30 CTA tasks ----
    if (blockIdx.x < 30) {
        int l = blockIdx.x / 5, b5 = blockIdx.x % 5;
        float* sq = sc; float* sk = sc + DD; float* satt = sc + DD + 7*DD;
        const float* kvb = g_kv + (size_t)(l*5 + b5)*7*1024;
        cp4(sq, g_q0 + (l*5 + b5)*DD, DD);
        for (int i = tid; i < 7*DD; i += NTHR) { int s = i >> 9, d = i & 511; sk[i] = kvb[s*1024 + d]; }
        __syncthreads();
        if (tid < 56) {
            int h = tid / 7, s = tid % 7;
            float a = 0.f;
            for (int d = 0; d < 64; d++) a += sq[h*64 + d] * sk[s*DD + h*64 + d];
            satt[tid] = a * 0.125f;
        }
        __syncthreads();
        if (tid < 8) {
            float m = -1e30f;
            for (int s = 0; s < 7; s++) m = fmaxf(m, satt[tid*7 + s]);
            float e[7], su = 0.f;
            for (int s = 0; s < 7; s++) { e[s] = expf(satt[tid*7 + s] - m); su += e[s]; }
            for (int s = 0; s < 7; s++) satt[tid*7 + s] = e[s] / su;
        }
        __syncthreads();
        for (int ch = tid; ch < DD; ch += NTHR) {
            int h = ch >> 6;
            float a = 0.f;
            for (int s = 0; s < 7; s++) a += satt[h*7 + s] * kvb[s*1024 + 512 + ch];
            g_ctx5[(l*5 + b5)*DD + ch] = a;
        }
    }
    gridbar(bbase, ++bi);

    // ---- P2b: verb msgs ----
    cp4(sc, g_ctx5, 30*DD);
    __syncthreads();
    for (int t = gw; t < NL*DD; t += NWARP) {
        float4 wv[4];
        if (t == gw) { wv[0]=pw[0]; wv[1]=pw[1]; wv[2]=pw[2]; wv[3]=pw[3]; }
        else ldw(out_w + ((size_t)(t >> 9)*DD + (t & 511))*DD, wv);
        int l = t >> 9, e = t & 511;
        float bias = out_b[l*DD + e];
        float res[5];
        dotK<5, DD>(wv, sc + l*5*DD, res);
        if (lane == 0)
#pragma unroll
            for (int j = 0; j < 5; j++)
                g_vm[(l*5 + j)*DD + e] = res[j] + bias;
    }
    gridbar(bbase, ++bi);

    // ---- P3: agg_verb ----
    cp4(sc, g_vm, 30*DD);
    __syncthreads();
    for (int t = gw; t < NL*DD; t += NWARP) {
        int l = t >> 9, e = t & 511;
        float a = dot_long<20>(a1w + ((size_t)l*DD + e)*2560, sc + l*5*DD);
        if (lane == 0) g_aggv[l*DD + e] = 1.f / (1.f + expf(-(a + a1b[l*DD + e])));
    }
    cp4(psx, feat, 7*DD);   // init persistent x = features[0]
    // preload F1(0) task
    {
        int t = gw;
        const float* rp = (t < TD) ? in_w + (size_t)t*DD
                                   : f1w1 + (size_t)(t - TD)*DD;
        ldw(rp, pw);
    }
    gridbar(bbase, ++bi);

    // ================= layer loop =================
    for (int l = 0; l < NL; l++) {
        // ---- F1: ssrc build + LN1 + qkv + FFN1-up ----
        {
            float* ssrc = sc;   // 7*512
            if (warp == 0) {
                if (l == 0) {
                    for (int j = 0; j < 16; j++) ssrc[j*32 + lane] = psx[j*32 + lane];
                } else {
                    const float* fb = f2b2 + (l-1)*DD;
                    ln_rowf([&](int i){ return g_yraw[i] + fb[i] + psh0[i]; },
                            ln4w + (l-1)*DD, ln4b + (l-1)*DD, ssrc);
                    for (int j = 0; j < 16; j++) psx[j*32 + lane] = ssrc[j*32 + lane];
                }
            } else if (warp < 7) {
                ln_rowf([&](int i){ return psx[warp*DD + i] + g_aggv[l*DD + i]; },
                        ln1w + l*DD, ln1b + l*DD, psh1 + (warp-1)*DD);
            } else if (warp < 13) {
                int r = warp - 6;   // 1..6
                for (int j = 0; j < 16; j++) {
                    int d = j*32 + lane;
                    ssrc[r*DD + d] = psx[r*DD + d] + role[(r-1)*DD + d];
                }
            } else {
                int base = (warp - 13) * 1024;   // 3 warps zero 3072 floats (rows 1-6)
                for (int j = 0; j < 32; j++) g_yraw[DD + base + j*32 + lane] = 0.f;
            }
            __syncthreads();
            for (int t = gw; t < TD + FF; t += NWARP) {
                float4 wv[4];
                if (t == gw) { wv[0]=pw[0]; wv[1]=pw[1]; wv[2]=pw[2]; wv[3]=pw[3]; }
                else {
                    const float* rp = (t < TD) ? in_w + ((size_t)l*TD + t)*DD
                                               : f1w1 + ((size_t)l*FF + (t - TD))*DD;
                    ldw(rp, wv);
                }
                if (t < TD) {
                    float res[7];
                    dotK<7, DD>(wv, ssrc, res);
                    if (lane == 0) {
                        float bias = in_b[l*TD + t];
#pragma unroll
                        for (int s = 0; s < 7; s++) g_qkv0[s*TD + t] = res[s] + bias;
                    }
                } else {
                    int e = t - TD;
                    float res[6];
                    dotK<6, DD>(wv, psh1, res);
                    if (lane == 0) {
                        float bias = f1b1[l*FF + e];
#pragma unroll
                        for (int r = 0; r < 6; r++)
                            g_hid[(r+1)*FF + e] = fmaxf(res[r] + bias, 0.f);
                    }
                }
            }
            pf_range(a2w + (size_t)l*DD*3072, DD*3072, gt);
            // preload F2 task
            const float* rp = (gw < 512)
                ? out_w + ((size_t)l*DD + gw)*DD
                : f1w2 + ((size_t)l*DD + ((gw-512) & 511))*FF + (((gw-512) >> 9) * 512);
            ldw(rp, pw);
        }
        gridbar(bbase, ++bi);

        // ---- F2: attention + msg (CTAs 0-31) | f1w2 segments (CTAs 32+) ----
        {
            if (blockIdx.x < 32) {
                float* sqkv = sc;            // 10752
                float* sctx = sc + 10752;    // 3072
                float* satt = sc + 13824;    // 336
                cp4(sqkv, g_qkv0, 7*TD);
                __syncthreads();
                for (int t = tid; t < 336; t += NTHR) {
                    int qi = t / 56, r = t % 56, h = r / 7, s = r % 7;
                    const float* qv = sqkv + (qi+1)*TD + h*64;
                    const float* kv = sqkv + s*TD + 512 + h*64;
                    float a0=0,a1=0,a2=0,a3=0;
#pragma unroll
                    for (int d = 0; d < 64; d += 4) {
                        a0 = fmaf(qv[d],   kv[d],   a0);
                        a1 = fmaf(qv[d+1], kv[d+1], a1);
                        a2 = fmaf(qv[d+2], kv[d+2], a2);
                        a3 = fmaf(qv[d+3], kv[d+3], a3);
                    }
                    satt[t] = ((a0+a1)+(a2+a3)) * 0.125f;
                }
                __syncthreads();
                if (tid < 48) {
                    float m = -1e30f;
                    for (int s = 0; s < 7; s++) m = fmaxf(m, satt[tid*7 + s]);
                    float e[7], su = 0.f;
                    for (int s = 0; s < 7; s++) { e[s] = expf(satt[tid*7 + s] - m); su += e[s]; }
                    for (int s = 0; s < 7; s++) satt[tid*7 + s] = e[s] / su;
                }
                __syncthreads();
                for (int i = tid; i < 6*DD; i += NTHR) {
                    int qi = i >> 9, ch = i & 511, h = ch >> 6;
                    float a = 0.f;
                    for (int s = 0; s < 7; s++) a += satt[qi*56 + h*7 + s] * sqkv[s*TD + 1024 + ch];
                    sctx[i] = a;
                }
                __syncthreads();
                {   // msg dot: one task per warp (gw < 512), weights preloaded
                    int t = gw;
                    float res[6];
                    dotK<6, DD>(pw, sctx, res);
                    if (lane == 0) {
                        float bias = out_b[l*DD + t];
#pragma unroll
                        for (int r = 0; r < 6; r++) g_msgN[r*DD + t] = res[r] + bias;
                    }
                }
            } else {
                float* shid = sc;   // 6*2048
                cp4(shid, g_hid + FF, 6*FF);
                if (blockIdx.x == 140)
                    for (int i = tid; i < DD; i += NTHR) g_aggnraw[i] = 0.f;
                __syncthreads();
                // f1w2 rows have FF=2048 floats -> 4 segments of 512 (u < 2048!)
                for (int u = gw - 512; u < 2048; u += (NWARP - 512)) {
                    int e = u & 511, s = u >> 9;
                    float4 wv[4];
                    if (u == gw - 512) { wv[0]=pw[0]; wv[1]=pw[1]; wv[2]=pw[2]; wv[3]=pw[3]; }
                    else ldw(f1w2 + ((size_t)l*DD + e)*FF + s*512, wv);
                    float res[6];
                    dotK<6, FF>(wv, shid + s*512, res);
                    if (lane == 0) {
                        float extra = (s == 0) ? f1b2[l*DD + e] : 0.f;
#pragma unroll
                        for (int r = 0; r < 6; r++) {
                            float add = res[r] + ((s == 0) ? (extra + psh1[r*DD + e]) : 0.f);
                            atomicAdd(&g_yraw[(r+1)*DD + e], add);
                        }
                    }
                }
            }
            pf_range(f2w1 + (size_t)l*FF*DD, FF*DD, gt);
            // preload F3 task (a2w segment)
            if (gw < 3072)
                ldw(a2w + ((size_t)l*DD + (gw & 511))*3072 + (gw >> 9)*512, pw);
        }
        gridbar(bbase, ++bi);

        // ---- F3: agg_noun segments (a2w rows = 3072 floats -> 6 segments) ----
        {
            float* smsg = sc;   // 6*512
            cp4(smsg, g_msgN, 6*DD);
            if (blockIdx.x == 140)
                for (int i = tid; i < DD; i += NTHR) g_yraw[i] = 0.f;
            __syncthreads();
            for (int u = gw; u < 3072; u += NWARP) {
                int e = u & 511, s = u >> 9;
                float4 wv[4];
                if (u == gw) { wv[0]=pw[0]; wv[1]=pw[1]; wv[2]=pw[2]; wv[3]=pw[3]; }
                else ldw(a2w + ((size_t)l*DD + e)*3072 + s*512, wv);
                float res[1];
                dotK<1, DD>(wv, smsg + s*DD, res);
                if (lane == 0) atomicAdd(&g_aggnraw[e], res[0]);
            }
            pf_range(f2w2 + (size_t)l*DD*FF, DD*FF, gt);
            // preload F4 task
            if (gw < FF) ldw(f2w1 + ((size_t)l*FF + gw)*DD, pw);
        }
        gridbar(bbase, ++bi);

        // ---- F4: LN3 + LN2 + FFN2-up ----
        {
            if (warp == 0) {
                const float* ab = a2b + l*DD;
                ln_rowf([&](int i){
                            float a = g_aggnraw[i] + ab[i];
                            return psx[i] + 1.f / (1.f + expf(-a));
                        }, ln3w + l*DD, ln3b + l*DD, psh0);
            } else if (warp < 7) {
                ln_rowf([&](int i){ return g_yraw[warp*DD + i]; },
                        ln2w + l*DD, ln2b + l*DD, psx + warp*DD);
            }
            __syncthreads();
            for (int t = gw; t < FF; t += NWARP) {
                float4 wv[4];
                if (t == gw) { wv[0]=pw[0]; wv[1]=pw[1]; wv[2]=pw[2]; wv[3]=pw[3]; }
                else ldw(f2w1 + ((size_t)l*FF + t)*DD, wv);
                float res[1];
                dotK<1, DD>(wv, psh0, res);
                if (lane == 0) g_hid[t] = fmaxf(res[0] + f2b1[l*FF + t], 0.f);
            }
            if (l + 1 < NL) pf_range(in_w + (size_t)(l+1)*TD*DD, TD*DD, gt);
            // preload F5 task (f2w2 segment)
            if (gw < 2048)
                ldw(f2w2 + ((size_t)l*DD + (gw & 511))*FF + (gw >> 9)*512, pw);
        }
        gridbar(bbase, ++bi);

        // ---- F5: FFN2-down segments (RAW partials only — bias+resid added by LN4 reader) ----
        {
            float* shid0 = sc;   // 2048
            cp4(shid0, g_hid, FF);
            __syncthreads();
            for (int u = gw; u < 2048; u += NWARP) {
                int e = u & 511, s = u >> 9;
                float4 wv[4];
                if (u == gw) { wv[0]=pw[0]; wv[1]=pw[1]; wv[2]=pw[2]; wv[3]=pw[3]; }
                else ldw(f2w2 + ((size_t)l*DD + e)*FF + s*512, wv);
                float res[1];
                dotK<1, DD>(wv, shid0 + s*DD, res);
                if (lane == 0) atomicAdd(&g_yraw[e], res[0]);
            }
            if (l + 1 < NL) {
                pf_range(f1w1 + (size_t)(l+1)*FF*DD, FF*DD, gt);
                // preload next F1 task
                int t = gw;
                const float* rp = (t < TD) ? in_w + ((size_t)(l+1)*TD + t)*DD
                                           : f1w1 + ((size_t)(l+1)*FF + (t - TD))*DD;
                ldw(rp, pw);
            }
        }
        gridbar(bbase, ++bi);
    }

    // ---- final output: LN4 row0, LN2 rows1-6 ----
    if (blockIdx.x == 0 && warp < 7) {
        if (warp == 0) {
            const float* fb = f2b2 + 5*DD;
            ln_rowf([&](int i){ return g_yraw[i] + fb[i] + psh0[i]; },
                    ln4w + 5*DD, ln4b + 5*DD, out);
        } else {
            ln_rowf([&](int i){ return g_yraw[warp*DD + i]; },
                    ln2w + 5*DD, ln2b + 5*DD, out + warp*DD);
        }
    }
}

#define SMEM_BYTES 102400

extern "C" void kernel_launch(void* const* d_in, const int* in_sizes, int n_in,
                              void* d_out, int out_size) {
    cudaFuncSetAttribute(fused_kernel, cudaFuncAttributeMaxDynamicSharedMemorySize, SMEM_BYTES);
    fused_kernel<<<NBLK, NTHR, SMEM_BYTES>>>(
        (const float*)d_in[0],  (const float*)d_in[1],
        (const float*)d_in[2],  (const float*)d_in[3],
        (const float*)d_in[4],  (const float*)d_in[5],
        (const float*)d_in[6],  (const float*)d_in[7],
        (const float*)d_in[8],  (const float*)d_in[9],
        (const float*)d_in[10], (const float*)d_in[11],
        (const float*)d_in[12], (const float*)d_in[13],
        (const float*)d_in[14], (const float*)d_in[15],
        (const float*)d_in[16], (const float*)d_in[17],
        (const float*)d_in[18], (const float*)d_in[19],
        (const float*)d_in[20], (const float*)d_in[21],
        (const float*)d_in[22], (const float*)d_in[23],
        (const float*)d_in[24], (const float*)d_in[25],
        (float*)d_out);
}